// round 2
// baseline (speedup 1.0000x reference)
#include <cuda_runtime.h>
#include <cuda_bf16.h>

// CoPE fused kernel: per row (b,h,i) of L=1024:
//   gates = sigmoid(attn_row), diag zeroed
//   pos   = clamp(suffix_sum(gates), 0, 63)
//   L[n]  = q_row . pos_emb[:, n]           (64x64 GEMV, in shared)
//   out   = L[ceil(pos)]*w + L[floor(pos)]*(1-w)
//
// HBM-bound: ~415 MB total traffic.

#define L_SEQ 1024
#define NPOS  64

__global__ __launch_bounds__(256) void cope_kernel(
    const float* __restrict__ query,      // [rows, 64]
    const float* __restrict__ attn,       // [rows, 1024]
    const float* __restrict__ pe,         // [64, 64] (d, n)
    float* __restrict__ out)              // [rows, 1024]
{
    const int row  = blockIdx.x;          // bh*1024 + i
    const int diag = row & (L_SEQ - 1);   // i
    const int t    = threadIdx.x;
    const int lane = t & 31;
    const int wid  = t >> 5;

    __shared__ float warpsum[8];
    __shared__ float qsh[64];
    __shared__ float Lp[4][64];
    __shared__ float Lg[64];

    // ---- load attn row (float4), sigmoid, zero diagonal ----
    const float4* arow = reinterpret_cast<const float4*>(attn + (size_t)row * L_SEQ);
    float4 v = arow[t];
    float g0 = 1.0f / (1.0f + __expf(-v.x));
    float g1 = 1.0f / (1.0f + __expf(-v.y));
    float g2 = 1.0f / (1.0f + __expf(-v.z));
    float g3 = 1.0f / (1.0f + __expf(-v.w));
    const int c0 = t << 2;
    if (c0     == diag) g0 = 0.0f;
    if (c0 + 1 == diag) g1 = 0.0f;
    if (c0 + 2 == diag) g2 = 0.0f;
    if (c0 + 3 == diag) g3 = 0.0f;
    const float s = g0 + g1 + g2 + g3;

    // ---- stage query row for the GEMV ----
    if (t < 64) qsh[t] = query[(size_t)row * 64 + t];

    // ---- warp inclusive scan of per-thread sums ----
    float incl = s;
    #pragma unroll
    for (int off = 1; off < 32; off <<= 1) {
        float nv = __shfl_up_sync(0xffffffffu, incl, off);
        if (lane >= off) incl += nv;
    }
    if (lane == 31) warpsum[wid] = incl;
    __syncthreads();   // warpsum + qsh visible

    // ---- GEMV partials: thread t handles n = t%64, d-chunk t/64 ----
    {
        const int n  = t & 63;
        const int db = t >> 6;          // 0..3
        float acc = 0.0f;
        #pragma unroll
        for (int dd = 0; dd < 16; dd++) {
            const int d = db * 16 + dd;
            acc = fmaf(qsh[d], __ldg(&pe[d * NPOS + n]), acc);
        }
        Lp[db][n] = acc;
    }

    // ---- finish block scan (register math, overlaps GEMV) ----
    float wpre = 0.0f, total = 0.0f;
    #pragma unroll
    for (int k = 0; k < 8; k++) {
        const float wsk = warpsum[k];
        total += wsk;
        if (k < wid) wpre += wsk;
    }
    const float excl = wpre + incl - s;   // exclusive prefix at element c0

    __syncthreads();   // Lp complete
    if (t < 64) Lg[t] = Lp[0][t] + Lp[1][t] + Lp[2][t] + Lp[3][t];
    __syncthreads();   // Lg complete

    // ---- suffix sums: suffix_incl[j] = total - prefix_excl[j] ----
    const float p0 = total - excl;
    const float p1 = p0 - g0;
    const float p2 = p1 - g1;
    const float p3 = p2 - g2;

    // ---- interpolate from shared Lg ----
    float4 o;
    {
        float p, pf, w; int fi, ci;
        p = fminf(fmaxf(p0, 0.0f), 63.0f); pf = floorf(p); w = p - pf;
        fi = (int)pf; ci = (int)ceilf(p);
        o.x = Lg[ci] * w + Lg[fi] * (1.0f - w);
        p = fminf(fmaxf(p1, 0.0f), 63.0f); pf = floorf(p); w = p - pf;
        fi = (int)pf; ci = (int)ceilf(p);
        o.y = Lg[ci] * w + Lg[fi] * (1.0f - w);
        p = fminf(fmaxf(p2, 0.0f), 63.0f); pf = floorf(p); w = p - pf;
        fi = (int)pf; ci = (int)ceilf(p);
        o.z = Lg[ci] * w + Lg[fi] * (1.0f - w);
        p = fminf(fmaxf(p3, 0.0f), 63.0f); pf = floorf(p); w = p - pf;
        fi = (int)pf; ci = (int)ceilf(p);
        o.w = Lg[ci] * w + Lg[fi] * (1.0f - w);
    }

    reinterpret_cast<float4*>(out + (size_t)row * L_SEQ)[t] = o;
}

extern "C" void kernel_launch(void* const* d_in, const int* in_sizes, int n_in,
                              void* d_out, int out_size) {
    const float* query = (const float*)d_in[0];   // [4,12,1024,64]
    const float* attn  = (const float*)d_in[1];   // [4,12,1024,1024]
    const float* pe    = (const float*)d_in[2];   // [64,64]
    float* out = (float*)d_out;                   // [4,12,1024,1024]

    const int rows = in_sizes[1] / L_SEQ;         // 4*12*1024 = 49152
    cope_kernel<<<rows, 256>>>(query, attn, pe, out);
}